// round 1
// baseline (speedup 1.0000x reference)
#include <cuda_runtime.h>
#include <math.h>

// ---------------- problem constants ----------------
#define DEPTH 2
#define DIM   1024
#define HEADS 16
#define DH    64
#define BATCH 8
#define NQ    256
#define JTOT  1088          // MEM*N + TEXT = 1024 + 64
#define MS    1024          // memory tokens
#define MROWS (BATCH*NQ)    // 2048  (x rows)
#define CROWS (BATCH*JTOT)  // 8704  (cond rows)
#define FFH   4096
#define SCALE 0.125f

// ---------------- scratch (device globals; no allocation allowed) -----------
__device__ float g_Q[MROWS * DIM];                 // 8 MB
__device__ float g_K[CROWS * DIM];                 // 35.6 MB
__device__ float g_V[CROWS * DIM];                 // 35.6 MB
__device__ float g_S[(long)BATCH * HEADS * NQ * JTOT]; // 142.6 MB
__device__ float g_O[MROWS * DIM];                 // 8 MB
__device__ float g_H[(long)MROWS * 2 * FFH];       // 67 MB
__device__ float g_Y[(long)MROWS * FFH];           // 33.5 MB

// ---------------- generic batched tiled SGEMM ----------------
// C[z] = alpha * A[z] @ B[z](^T) (+ bias[col]) (+ Cadd[z])
// z decomposed as (zb, zh) with zb = z / HB, zh = z % HB; per-matrix two strides.
// Tiles: 64x64x16, 256 threads, 4x4 per thread. All dims assumed multiples.
template <bool TRANSB>
__global__ void gemm64(const float* __restrict__ A, const float* __restrict__ B,
                       float* __restrict__ C, const float* __restrict__ Cadd,
                       const float* __restrict__ bias,
                       int M, int N, int K, int lda, int ldb, int ldc,
                       long long sA1, long long sA2,
                       long long sB1, long long sB2,
                       long long sC1, long long sC2,
                       int HB, float alpha)
{
    int z  = blockIdx.z;
    int zb = z / HB, zh = z - zb * HB;
    A += zb * sA1 + zh * sA2;
    B += zb * sB1 + zh * sB2;
    C += zb * sC1 + zh * sC2;
    if (Cadd) Cadd += zb * sC1 + zh * sC2;

    __shared__ float As[16][64];
    __shared__ float Bs[16][64];

    const int tid = threadIdx.x;
    const int tx = tid & 15, ty = tid >> 4;
    const int bm = blockIdx.y, bn = blockIdx.x;

    float acc[4][4] = {};

    const int ar = tid >> 2;          // 0..63 (row within A tile)
    const int ac = (tid & 3) * 4;     // 0,4,8,12 (k within A tile)
    const float* Aptr = A + (long long)(bm * 64 + ar) * lda + ac;

    for (int k0 = 0; k0 < K; k0 += 16) {
        float4 av = *(const float4*)(Aptr);
        Aptr += 16;
        As[ac + 0][ar] = av.x; As[ac + 1][ar] = av.y;
        As[ac + 2][ar] = av.z; As[ac + 3][ar] = av.w;

        if (TRANSB) {
            // B is [N,K] row-major; need Bs[k][n]
            int nr = tid >> 2;            // 0..63 (n within tile)
            int kc = (tid & 3) * 4;       // k within tile
            float4 bv = *(const float4*)(B + (long long)(bn * 64 + nr) * ldb + k0 + kc);
            Bs[kc + 0][nr] = bv.x; Bs[kc + 1][nr] = bv.y;
            Bs[kc + 2][nr] = bv.z; Bs[kc + 3][nr] = bv.w;
        } else {
            int br = tid >> 4;            // 0..15 (k within tile)
            int bc = (tid & 15) * 4;      // n within tile
            float4 bv = *(const float4*)(B + (long long)(k0 + br) * ldb + bn * 64 + bc);
            *(float4*)&Bs[br][bc] = bv;
        }
        __syncthreads();

        #pragma unroll
        for (int kk = 0; kk < 16; kk++) {
            float4 a4 = *(const float4*)&As[kk][ty * 4];
            float4 b4 = *(const float4*)&Bs[kk][tx * 4];
            float a[4] = {a4.x, a4.y, a4.z, a4.w};
            float b[4] = {b4.x, b4.y, b4.z, b4.w};
            #pragma unroll
            for (int i = 0; i < 4; i++)
                #pragma unroll
                for (int j = 0; j < 4; j++)
                    acc[i][j] += a[i] * b[j];
        }
        __syncthreads();
    }

    #pragma unroll
    for (int i = 0; i < 4; i++) {
        int row = bm * 64 + ty * 4 + i;
        #pragma unroll
        for (int j = 0; j < 4; j++) {
            int col = bn * 64 + tx * 4 + j;
            float v = alpha * acc[i][j];
            if (bias) v += bias[col];
            if (Cadd) v += Cadd[(long long)row * ldc + col];
            C[(long long)row * ldc + col] = v;
        }
    }
}

// ---------------- rotary on Q ----------------
// Q layout: [B*N, H*DH]; src_freq: [N, DH]
__global__ void rope_q_kernel(float* __restrict__ Q, const float* __restrict__ src_freq)
{
    long idx = (long)blockIdx.x * blockDim.x + threadIdx.x;  // over 2048*512 pairs
    if (idx >= (long)MROWS * (DIM / 2)) return;
    int row = (int)(idx >> 9);      // /512
    int pd  = (int)(idx & 511);
    int col = pd * 2;
    int n = row & (NQ - 1);
    int d = col & (DH - 1);
    float f0 = src_freq[n * DH + d];
    float f1 = src_freq[n * DH + d + 1];
    float* p = Q + (long long)row * DIM + col;
    float q0 = p[0], q1 = p[1];
    p[0] = q0 * cosf(f0) - q1 * sinf(f0);
    p[1] = q1 * cosf(f1) + q0 * sinf(f1);
}

// ---------------- RPE bias + rotary on memory part of K ----------------
// K layout: [B*JTOT, H*DH]; tgt_freq: [MS, DH]; rpe_l: [405,16]; rel_idx: [4]
__global__ void rope_bias_k_kernel(float* __restrict__ K,
                                   const float* __restrict__ tgt_freq,
                                   const float* __restrict__ rpe_l,
                                   const int* __restrict__ rel_idx)
{
    long idx = (long)blockIdx.x * blockDim.x + threadIdx.x;  // over 8*1024*512 pairs
    if (idx >= (long)BATCH * MS * (DIM / 2)) return;
    int b  = (int)(idx / ((long)MS * (DIM / 2)));
    int r  = (int)(idx % ((long)MS * (DIM / 2)));
    int j  = r >> 9;          // memory token index (< MS)
    int pd = r & 511;
    int col = pd * 2;
    int h = col >> 6;
    int d = col & (DH - 1);
    int mem = j >> 8;         // j / N
    float bias = rpe_l[rel_idx[mem] * HEADS + h];
    float f0 = tgt_freq[j * DH + d];
    float f1 = tgt_freq[j * DH + d + 1];
    float* p = K + ((long long)b * JTOT + j) * DIM + col;
    float k0 = p[0] + bias, k1 = p[1] + bias;
    p[0] = k0 * cosf(f0) - k1 * sinf(f0);
    p[1] = k1 * cosf(f1) + k0 * sinf(f1);
}

// ---------------- row softmax (n = 1088 per row) ----------------
__inline__ __device__ float warpMax(float v) {
    #pragma unroll
    for (int o = 16; o > 0; o >>= 1) v = fmaxf(v, __shfl_xor_sync(0xffffffffu, v, o));
    return v;
}
__inline__ __device__ float warpSum(float v) {
    #pragma unroll
    for (int o = 16; o > 0; o >>= 1) v += __shfl_xor_sync(0xffffffffu, v, o);
    return v;
}

__global__ void softmax_rows(float* __restrict__ S, int n)
{
    long row = blockIdx.x;
    float* p = S + row * n;
    int tid = threadIdx.x;           // 128 threads
    int wid = tid >> 5, lane = tid & 31;
    __shared__ float red[4];

    float v[9];
    int cnt = 0;
    float m = -INFINITY;
    for (int j = tid; j < n; j += 128) {
        v[cnt] = p[j];
        m = fmaxf(m, v[cnt]);
        cnt++;
    }
    m = warpMax(m);
    if (lane == 0) red[wid] = m;
    __syncthreads();
    m = fmaxf(fmaxf(red[0], red[1]), fmaxf(red[2], red[3]));

    float s = 0.f;
    for (int i = 0; i < cnt; i++) {
        v[i] = expf(v[i] - m);
        s += v[i];
    }
    s = warpSum(s);
    __syncthreads();
    if (lane == 0) red[wid] = s;
    __syncthreads();
    s = red[0] + red[1] + red[2] + red[3];
    float inv = 1.0f / s;

    int i = 0;
    for (int j = tid; j < n; j += 128) p[j] = v[i++] * inv;
}

// ---------------- GEGLU: y = a * gelu_exact(g) ----------------
__global__ void geglu_kernel(const float* __restrict__ H, float* __restrict__ Y)
{
    long idx = (long)blockIdx.x * blockDim.x + threadIdx.x;  // over 2048*4096
    if (idx >= (long)MROWS * FFH) return;
    int row = (int)(idx >> 12);
    int c   = (int)(idx & (FFH - 1));
    const float* hr = H + (long long)row * (2 * FFH);
    float a = hr[c];
    float g = hr[FFH + c];
    float ge = 0.5f * g * (1.0f + erff(g * 0.70710678118654752f));
    Y[idx] = a * ge;
}

// ---------------- launcher ----------------
extern "C" void kernel_launch(void* const* d_in, const int* in_sizes, int n_in,
                              void* d_out, int out_size)
{
    const float* x    = (const float*)d_in[0];
    const float* cond = (const float*)d_in[1];
    const float* Wq   = (const float*)d_in[2];
    const float* Wk   = (const float*)d_in[3];
    const float* Wv   = (const float*)d_in[4];
    const float* Wo   = (const float*)d_in[5];
    const float* bo   = (const float*)d_in[6];
    const float* rpe  = (const float*)d_in[7];
    const float* W1   = (const float*)d_in[8];
    const float* b1   = (const float*)d_in[9];
    const float* W2   = (const float*)d_in[10];
    const float* b2   = (const float*)d_in[11];
    const float* srcf = (const float*)d_in[12];
    const float* tgtf = (const float*)d_in[13];
    const int*   reli = (const int*)d_in[14];
    float* xo = (float*)d_out;

    float *Q, *K, *V, *S, *O, *H, *Y;
    cudaGetSymbolAddress((void**)&Q, g_Q);
    cudaGetSymbolAddress((void**)&K, g_K);
    cudaGetSymbolAddress((void**)&V, g_V);
    cudaGetSymbolAddress((void**)&S, g_S);
    cudaGetSymbolAddress((void**)&O, g_O);
    cudaGetSymbolAddress((void**)&H, g_H);
    cudaGetSymbolAddress((void**)&Y, g_Y);

    // x -> output buffer (residual stream lives there)
    cudaMemcpyAsync(xo, x, (size_t)MROWS * DIM * sizeof(float),
                    cudaMemcpyDeviceToDevice, 0);

    const long long SBH = (long long)NQ * JTOT;        // 278528, per-(b,h) score tile
    const long long SB  = SBH * HEADS;                 // per-batch score stride

    for (int l = 0; l < DEPTH; l++) {
        const float* wq = Wq + (long long)l * DIM * DIM;
        const float* wk = Wk + (long long)l * DIM * DIM;
        const float* wv = Wv + (long long)l * DIM * DIM;
        const float* wo = Wo + (long long)l * DIM * DIM;
        const float* bol = bo + l * DIM;
        const float* rpel = rpe + (long long)l * 405 * HEADS;
        const float* w1 = W1 + (long long)l * DIM * (2 * FFH);
        const float* b1l = b1 + (long long)l * (2 * FFH);
        const float* w2 = W2 + (long long)l * FFH * DIM;
        const float* b2l = b2 + l * DIM;

        // Q = x @ Wq[l]   [2048,1024]
        gemm64<false><<<dim3(DIM / 64, MROWS / 64, 1), 256>>>(
            xo, wq, Q, nullptr, nullptr,
            MROWS, DIM, DIM, DIM, DIM, DIM,
            0, 0, 0, 0, 0, 0, 1, 1.0f);
        // K = cond @ Wk[l]  [8704,1024]
        gemm64<false><<<dim3(DIM / 64, CROWS / 64, 1), 256>>>(
            cond, wk, K, nullptr, nullptr,
            CROWS, DIM, DIM, DIM, DIM, DIM,
            0, 0, 0, 0, 0, 0, 1, 1.0f);
        // V = cond @ Wv[l]
        gemm64<false><<<dim3(DIM / 64, CROWS / 64, 1), 256>>>(
            cond, wv, V, nullptr, nullptr,
            CROWS, DIM, DIM, DIM, DIM, DIM,
            0, 0, 0, 0, 0, 0, 1, 1.0f);

        // rotary on Q
        {
            long tot = (long)MROWS * (DIM / 2);
            rope_q_kernel<<<(unsigned)((tot + 255) / 256), 256>>>(Q, srcf);
        }
        // bias + rotary on memory part of K
        {
            long tot = (long)BATCH * MS * (DIM / 2);
            rope_bias_k_kernel<<<(unsigned)((tot + 255) / 256), 256>>>(K, tgtf, rpel, reli);
        }

        // S = SCALE * Q_bh @ K_bh^T   batched over 128 (b,h)
        gemm64<true><<<dim3(JTOT / 64, NQ / 64, BATCH * HEADS), 256>>>(
            Q, K, S, nullptr, nullptr,
            NQ, JTOT, DH, DIM, DIM, JTOT,
            (long long)NQ * DIM, DH,            // A: per-b, per-h
            (long long)JTOT * DIM, DH,          // B: per-b, per-h
            SB, SBH,                            // C: per-b, per-h
            HEADS, SCALE);

        // softmax rows
        softmax_rows<<<(unsigned)(BATCH * HEADS * NQ), 128>>>(S, JTOT);

        // O_bh = S_bh @ V_bh  -> packed directly as [b, n, h*64+d]
        gemm64<false><<<dim3(DH / 64, NQ / 64, BATCH * HEADS), 256>>>(
            S, V, O, nullptr, nullptr,
            NQ, DH, JTOT, JTOT, DIM, DIM,
            SB, SBH,
            (long long)JTOT * DIM, DH,
            (long long)NQ * DIM, DH,
            HEADS, 1.0f);

        // x = x + O @ Wo[l] + bo[l]
        gemm64<false><<<dim3(DIM / 64, MROWS / 64, 1), 256>>>(
            O, wo, xo, xo, bol,
            MROWS, DIM, DIM, DIM, DIM, DIM,
            0, 0, 0, 0, 0, 0, 1, 1.0f);

        // H = x @ W1[l] + b1[l]   [2048, 8192]
        gemm64<false><<<dim3((2 * FFH) / 64, MROWS / 64, 1), 256>>>(
            xo, w1, H, nullptr, b1l,
            MROWS, 2 * FFH, DIM, DIM, 2 * FFH, 2 * FFH,
            0, 0, 0, 0, 0, 0, 1, 1.0f);

        // Y = a * gelu(g)
        {
            long tot = (long)MROWS * FFH;
            geglu_kernel<<<(unsigned)((tot + 255) / 256), 256>>>(H, Y);
        }

        // x = x + Y @ W2[l] + b2[l]
        gemm64<false><<<dim3(DIM / 64, MROWS / 64, 1), 256>>>(
            Y, w2, xo, xo, b2l,
            MROWS, DIM, FFH, FFH, DIM, DIM,
            0, 0, 0, 0, 0, 0, 1, 1.0f);
    }
}

// round 2
// speedup vs baseline: 2.3790x; 2.3790x over previous
#include <cuda_runtime.h>
#include <math.h>
#include <stdint.h>

// ---------------- problem constants ----------------
#define DEPTH 2
#define DIM   1024
#define HEADS 16
#define DH    64
#define BATCH 8
#define NQ    256
#define JTOT  1088          // MEM*N + TEXT = 1024 + 64
#define MS    1024          // memory tokens
#define MROWS (BATCH*NQ)    // 2048
#define CROWS (BATCH*JTOT)  // 8704
#define FFH   4096
#define SCALE 0.125f

// ---------------- scratch ----------------
__device__ float g_Q[MROWS * DIM];
__device__ float g_K[CROWS * DIM];
__device__ float g_V[CROWS * DIM];
__device__ float g_S[(long)BATCH * HEADS * NQ * JTOT];
__device__ float g_O[MROWS * DIM];
__device__ float g_H[(long)MROWS * 2 * FFH];
__device__ float g_Y[(long)MROWS * FFH];

// ---------------- tf32 helpers ----------------
__device__ __forceinline__ uint32_t f2tf32(float f) {
    uint32_t r;
    asm("cvt.rna.tf32.f32 %0, %1;" : "=r"(r) : "f"(f));
    return r;
}

__device__ __forceinline__ void mma_tf32(float* c, const uint32_t* a, const uint32_t* b) {
    asm volatile(
        "mma.sync.aligned.m16n8k8.row.col.f32.tf32.tf32.f32 "
        "{%0,%1,%2,%3}, {%4,%5,%6,%7}, {%8,%9}, {%0,%1,%2,%3};"
        : "+f"(c[0]), "+f"(c[1]), "+f"(c[2]), "+f"(c[3])
        : "r"(a[0]), "r"(a[1]), "r"(a[2]), "r"(a[3]), "r"(b[0]), "r"(b[1]));
}

// ---------------- tf32 tensor-core batched GEMM ----------------
// C[z] = alpha * A[z] @ B[z](^T) (+ bias[col]) (+ Cadd[z])
// BM=128, BK=32, BN in {128,64}. 256 threads. All dims exact multiples.
template <int BN, bool TRANSB>
__global__ __launch_bounds__(256)
void gemm_mma(const float* __restrict__ A, const float* __restrict__ B,
              float* __restrict__ C, const float* __restrict__ Cadd,
              const float* __restrict__ bias,
              int M, int N, int K, int lda, int ldb, int ldc,
              long long sA1, long long sA2,
              long long sB1, long long sB2,
              long long sC1, long long sC2,
              int HB, float alpha)
{
    constexpr int BM = 128, BK = 32;
    constexpr int LDAS = BM + 4;              // 132 floats; rows 16B-aligned
    constexpr int LDBS = BN + 4;
    constexpr int WN = (BN == 128) ? 4 : 2;
    constexpr int WM = 8 / WN;                // 2 or 4
    constexpr int WTM = BM / WM;              // 64 or 32
    constexpr int WTN = BN / WN;              // 32
    constexpr int MI = WTM / 16;              // 4 or 2
    constexpr int NI = WTN / 8;               // 4
    constexpr int NBV = BN / 32;              // float4s of B per thread (4 or 2)
    constexpr int KSTEP = 1024 / BN;          // row step for non-trans B load

    __shared__ uint32_t As[BK * LDAS];
    __shared__ uint32_t Bs[BK * LDBS];

    const int z = blockIdx.z;
    const int zb = z / HB, zh = z - zb * HB;
    A += zb * sA1 + zh * sA2;
    B += zb * sB1 + zh * sB2;
    C += zb * sC1 + zh * sC2;
    if (Cadd) Cadd += zb * sC1 + zh * sC2;

    const int tid  = threadIdx.x;
    const int warp = tid >> 5, lane = tid & 31;
    const int wm = warp / WN, wn = warp % WN;
    const int g = lane >> 2, t = lane & 3;

    const int bm0 = blockIdx.y * BM;
    const int bn0 = blockIdx.x * BN;

    // A global-load addressing: 4 float4 per thread
    const int arow = tid >> 3;            // 0..31
    const int acol = (tid & 7) * 4;       // 0..28
    // B addressing
    const int nb = tid >> 3;              // trans: n row 0..31
    const int k4 = (tid & 7);             // trans: k group
    const int kb = tid / (BN / 4);        // non-trans: k row
    const int cb = tid % (BN / 4);        // non-trans: col group

    float4 areg[4];
    float4 breg[NBV];

    auto loadA = [&](int k0) {
        #pragma unroll
        for (int i = 0; i < 4; i++)
            areg[i] = *(const float4*)(A + (long long)(bm0 + arow + i * 32) * lda + k0 + acol);
    };
    auto storeA = [&]() {
        #pragma unroll
        for (int i = 0; i < 4; i++) {
            int r = arow + i * 32;
            As[(acol + 0) * LDAS + r] = f2tf32(areg[i].x);
            As[(acol + 1) * LDAS + r] = f2tf32(areg[i].y);
            As[(acol + 2) * LDAS + r] = f2tf32(areg[i].z);
            As[(acol + 3) * LDAS + r] = f2tf32(areg[i].w);
        }
    };
    auto loadB = [&](int k0) {
        if (TRANSB) {
            #pragma unroll
            for (int i = 0; i < NBV; i++)
                breg[i] = *(const float4*)(B + (long long)(bn0 + nb + i * 32) * ldb + k0 + k4 * 4);
        } else {
            #pragma unroll
            for (int i = 0; i < NBV; i++)
                breg[i] = *(const float4*)(B + (long long)(k0 + kb + i * KSTEP) * ldb + bn0 + cb * 4);
        }
    };
    auto storeB = [&]() {
        if (TRANSB) {
            #pragma unroll
            for (int i = 0; i < NBV; i++) {
                int n = nb + i * 32;
                Bs[(k4 * 4 + 0) * LDBS + n] = f2tf32(breg[i].x);
                Bs[(k4 * 4 + 1) * LDBS + n] = f2tf32(breg[i].y);
                Bs[(k4 * 4 + 2) * LDBS + n] = f2tf32(breg[i].z);
                Bs[(k4 * 4 + 3) * LDBS + n] = f2tf32(breg[i].w);
            }
        } else {
            #pragma unroll
            for (int i = 0; i < NBV; i++) {
                uint4 u;
                u.x = f2tf32(breg[i].x); u.y = f2tf32(breg[i].y);
                u.z = f2tf32(breg[i].z); u.w = f2tf32(breg[i].w);
                *(uint4*)&Bs[(kb + i * KSTEP) * LDBS + cb * 4] = u;
            }
        }
    };

    float acc[MI][NI][4];
    #pragma unroll
    for (int mi = 0; mi < MI; mi++)
        #pragma unroll
        for (int ni = 0; ni < NI; ni++)
            #pragma unroll
            for (int q = 0; q < 4; q++) acc[mi][ni][q] = 0.f;

    // prologue
    loadA(0); loadB(0);
    storeA(); storeB();
    __syncthreads();

    const int KT = K / BK;
    for (int kt = 0; kt < KT; kt++) {
        if (kt + 1 < KT) { loadA((kt + 1) * BK); loadB((kt + 1) * BK); }

        #pragma unroll
        for (int kk = 0; kk < BK; kk += 8) {
            uint32_t af[MI][4], bf[NI][2];
            #pragma unroll
            for (int mi = 0; mi < MI; mi++) {
                int mbase = wm * WTM + mi * 16;
                af[mi][0] = As[(kk + t) * LDAS + mbase + g];
                af[mi][1] = As[(kk + t) * LDAS + mbase + g + 8];
                af[mi][2] = As[(kk + t + 4) * LDAS + mbase + g];
                af[mi][3] = As[(kk + t + 4) * LDAS + mbase + g + 8];
            }
            #pragma unroll
            for (int ni = 0; ni < NI; ni++) {
                int nbase = wn * WTN + ni * 8;
                bf[ni][0] = Bs[(kk + t) * LDBS + nbase + g];
                bf[ni][1] = Bs[(kk + t + 4) * LDBS + nbase + g];
            }
            #pragma unroll
            for (int mi = 0; mi < MI; mi++)
                #pragma unroll
                for (int ni = 0; ni < NI; ni++)
                    mma_tf32(acc[mi][ni], af[mi], bf[ni]);
        }
        __syncthreads();
        if (kt + 1 < KT) { storeA(); storeB(); }
        __syncthreads();
    }

    // epilogue
    #pragma unroll
    for (int mi = 0; mi < MI; mi++) {
        int row0 = bm0 + wm * WTM + mi * 16 + g;
        #pragma unroll
        for (int ni = 0; ni < NI; ni++) {
            int col = bn0 + wn * WTN + ni * 8 + 2 * t;
            float v0 = alpha * acc[mi][ni][0];
            float v1 = alpha * acc[mi][ni][1];
            float v2 = alpha * acc[mi][ni][2];
            float v3 = alpha * acc[mi][ni][3];
            if (bias) { float b0 = bias[col], b1 = bias[col + 1]; v0 += b0; v1 += b1; v2 += b0; v3 += b1; }
            if (Cadd) {
                const float2 c0 = *(const float2*)(Cadd + (long long)row0 * ldc + col);
                const float2 c1 = *(const float2*)(Cadd + (long long)(row0 + 8) * ldc + col);
                v0 += c0.x; v1 += c0.y; v2 += c1.x; v3 += c1.y;
            }
            *(float2*)(C + (long long)row0 * ldc + col) = make_float2(v0, v1);
            *(float2*)(C + (long long)(row0 + 8) * ldc + col) = make_float2(v2, v3);
        }
    }
}

// ---------------- rotary on Q ----------------
__global__ void rope_q_kernel(float* __restrict__ Q, const float* __restrict__ src_freq)
{
    long idx = (long)blockIdx.x * blockDim.x + threadIdx.x;
    if (idx >= (long)MROWS * (DIM / 2)) return;
    int row = (int)(idx >> 9);
    int pd  = (int)(idx & 511);
    int col = pd * 2;
    int n = row & (NQ - 1);
    int d = col & (DH - 1);
    float f0 = src_freq[n * DH + d];
    float f1 = src_freq[n * DH + d + 1];
    float* p = Q + (long long)row * DIM + col;
    float q0 = p[0], q1 = p[1];
    p[0] = q0 * cosf(f0) - q1 * sinf(f0);
    p[1] = q1 * cosf(f1) + q0 * sinf(f1);
}

// ---------------- RPE bias + rotary on memory part of K ----------------
__global__ void rope_bias_k_kernel(float* __restrict__ K,
                                   const float* __restrict__ tgt_freq,
                                   const float* __restrict__ rpe_l,
                                   const int* __restrict__ rel_idx)
{
    long idx = (long)blockIdx.x * blockDim.x + threadIdx.x;
    if (idx >= (long)BATCH * MS * (DIM / 2)) return;
    int b  = (int)(idx / ((long)MS * (DIM / 2)));
    int r  = (int)(idx % ((long)MS * (DIM / 2)));
    int j  = r >> 9;
    int pd = r & 511;
    int col = pd * 2;
    int h = col >> 6;
    int d = col & (DH - 1);
    int mem = j >> 8;
    float bias = rpe_l[rel_idx[mem] * HEADS + h];
    float f0 = tgt_freq[j * DH + d];
    float f1 = tgt_freq[j * DH + d + 1];
    float* p = K + ((long long)b * JTOT + j) * DIM + col;
    float k0 = p[0] + bias, k1 = p[1] + bias;
    p[0] = k0 * cosf(f0) - k1 * sinf(f0);
    p[1] = k1 * cosf(f1) + k0 * sinf(f1);
}

// ---------------- row softmax ----------------
__inline__ __device__ float warpMax(float v) {
    #pragma unroll
    for (int o = 16; o > 0; o >>= 1) v = fmaxf(v, __shfl_xor_sync(0xffffffffu, v, o));
    return v;
}
__inline__ __device__ float warpSum(float v) {
    #pragma unroll
    for (int o = 16; o > 0; o >>= 1) v += __shfl_xor_sync(0xffffffffu, v, o);
    return v;
}

__global__ void softmax_rows(float* __restrict__ S, int n)
{
    long row = blockIdx.x;
    float* p = S + row * n;
    int tid = threadIdx.x;
    int wid = tid >> 5, lane = tid & 31;
    __shared__ float red[4];

    float v[9];
    int cnt = 0;
    float m = -INFINITY;
    for (int j = tid; j < n; j += 128) {
        v[cnt] = p[j];
        m = fmaxf(m, v[cnt]);
        cnt++;
    }
    m = warpMax(m);
    if (lane == 0) red[wid] = m;
    __syncthreads();
    m = fmaxf(fmaxf(red[0], red[1]), fmaxf(red[2], red[3]));

    float s = 0.f;
    for (int i = 0; i < cnt; i++) {
        v[i] = expf(v[i] - m);
        s += v[i];
    }
    s = warpSum(s);
    __syncthreads();
    if (lane == 0) red[wid] = s;
    __syncthreads();
    s = red[0] + red[1] + red[2] + red[3];
    float inv = 1.0f / s;

    int i = 0;
    for (int j = tid; j < n; j += 128) p[j] = v[i++] * inv;
}

// ---------------- GEGLU ----------------
__global__ void geglu_kernel(const float* __restrict__ H, float* __restrict__ Y)
{
    long idx = (long)blockIdx.x * blockDim.x + threadIdx.x;
    if (idx >= (long)MROWS * FFH) return;
    int row = (int)(idx >> 12);
    int c   = (int)(idx & (FFH - 1));
    const float* hr = H + (long long)row * (2 * FFH);
    float a = hr[c];
    float gg = hr[FFH + c];
    float ge = 0.5f * gg * (1.0f + erff(gg * 0.70710678118654752f));
    Y[idx] = a * ge;
}

// ---------------- launcher ----------------
extern "C" void kernel_launch(void* const* d_in, const int* in_sizes, int n_in,
                              void* d_out, int out_size)
{
    const float* x    = (const float*)d_in[0];
    const float* cond = (const float*)d_in[1];
    const float* Wq   = (const float*)d_in[2];
    const float* Wk   = (const float*)d_in[3];
    const float* Wv   = (const float*)d_in[4];
    const float* Wo   = (const float*)d_in[5];
    const float* bo   = (const float*)d_in[6];
    const float* rpe  = (const float*)d_in[7];
    const float* W1   = (const float*)d_in[8];
    const float* b1   = (const float*)d_in[9];
    const float* W2   = (const float*)d_in[10];
    const float* b2   = (const float*)d_in[11];
    const float* srcf = (const float*)d_in[12];
    const float* tgtf = (const float*)d_in[13];
    const int*   reli = (const int*)d_in[14];
    float* xo = (float*)d_out;

    float *Q, *K, *V, *S, *O, *H, *Y;
    cudaGetSymbolAddress((void**)&Q, g_Q);
    cudaGetSymbolAddress((void**)&K, g_K);
    cudaGetSymbolAddress((void**)&V, g_V);
    cudaGetSymbolAddress((void**)&S, g_S);
    cudaGetSymbolAddress((void**)&O, g_O);
    cudaGetSymbolAddress((void**)&H, g_H);
    cudaGetSymbolAddress((void**)&Y, g_Y);

    cudaMemcpyAsync(xo, x, (size_t)MROWS * DIM * sizeof(float),
                    cudaMemcpyDeviceToDevice, 0);

    const long long SBH = (long long)NQ * JTOT;
    const long long SB  = SBH * HEADS;

    for (int l = 0; l < DEPTH; l++) {
        const float* wq = Wq + (long long)l * DIM * DIM;
        const float* wk = Wk + (long long)l * DIM * DIM;
        const float* wv = Wv + (long long)l * DIM * DIM;
        const float* wo = Wo + (long long)l * DIM * DIM;
        const float* bol = bo + l * DIM;
        const float* rpel = rpe + (long long)l * 405 * HEADS;
        const float* w1 = W1 + (long long)l * DIM * (2 * FFH);
        const float* b1l = b1 + (long long)l * (2 * FFH);
        const float* w2 = W2 + (long long)l * FFH * DIM;
        const float* b2l = b2 + l * DIM;

        // Q = x @ Wq[l]
        gemm_mma<128, false><<<dim3(DIM / 128, MROWS / 128, 1), 256>>>(
            xo, wq, Q, nullptr, nullptr,
            MROWS, DIM, DIM, DIM, DIM, DIM,
            0, 0, 0, 0, 0, 0, 1, 1.0f);
        // K = cond @ Wk[l]
        gemm_mma<128, false><<<dim3(DIM / 128, CROWS / 128, 1), 256>>>(
            cond, wk, K, nullptr, nullptr,
            CROWS, DIM, DIM, DIM, DIM, DIM,
            0, 0, 0, 0, 0, 0, 1, 1.0f);
        // V = cond @ Wv[l]
        gemm_mma<128, false><<<dim3(DIM / 128, CROWS / 128, 1), 256>>>(
            cond, wv, V, nullptr, nullptr,
            CROWS, DIM, DIM, DIM, DIM, DIM,
            0, 0, 0, 0, 0, 0, 1, 1.0f);

        // rotary on Q
        {
            long tot = (long)MROWS * (DIM / 2);
            rope_q_kernel<<<(unsigned)((tot + 255) / 256), 256>>>(Q, srcf);
        }
        // bias + rotary on memory part of K
        {
            long tot = (long)BATCH * MS * (DIM / 2);
            rope_bias_k_kernel<<<(unsigned)((tot + 255) / 256), 256>>>(K, tgtf, rpel, reli);
        }

        // S = SCALE * Q_bh @ K_bh^T
        gemm_mma<64, true><<<dim3(JTOT / 64, NQ / 128, BATCH * HEADS), 256>>>(
            Q, K, S, nullptr, nullptr,
            NQ, JTOT, DH, DIM, DIM, JTOT,
            (long long)NQ * DIM, DH,
            (long long)JTOT * DIM, DH,
            SB, SBH,
            HEADS, SCALE);

        // softmax
        softmax_rows<<<(unsigned)(BATCH * HEADS * NQ), 128>>>(S, JTOT);

        // O_bh = S_bh @ V_bh
        gemm_mma<64, false><<<dim3(DH / 64, NQ / 128, BATCH * HEADS), 256>>>(
            S, V, O, nullptr, nullptr,
            NQ, DH, JTOT, JTOT, DIM, DIM,
            SB, SBH,
            (long long)JTOT * DIM, DH,
            (long long)NQ * DIM, DH,
            HEADS, 1.0f);

        // x = x + O @ Wo[l] + bo[l]
        gemm_mma<128, false><<<dim3(DIM / 128, MROWS / 128, 1), 256>>>(
            O, wo, xo, xo, bol,
            MROWS, DIM, DIM, DIM, DIM, DIM,
            0, 0, 0, 0, 0, 0, 1, 1.0f);

        // H = x @ W1[l] + b1[l]
        gemm_mma<128, false><<<dim3((2 * FFH) / 128, MROWS / 128, 1), 256>>>(
            xo, w1, H, nullptr, b1l,
            MROWS, 2 * FFH, DIM, DIM, 2 * FFH, 2 * FFH,
            0, 0, 0, 0, 0, 0, 1, 1.0f);

        // GEGLU
        {
            long tot = (long)MROWS * FFH;
            geglu_kernel<<<(unsigned)((tot + 255) / 256), 256>>>(H, Y);
        }

        // x = x + Y @ W2[l] + b2[l]
        gemm_mma<128, false><<<dim3(DIM / 128, MROWS / 128, 1), 256>>>(
            Y, w2, xo, xo, b2l,
            MROWS, DIM, FFH, FFH, DIM, DIM,
            0, 0, 0, 0, 0, 0, 1, 1.0f);
    }
}

// round 3
// speedup vs baseline: 3.8067x; 1.6001x over previous
#include <cuda_runtime.h>
#include <math.h>
#include <stdint.h>

// ---------------- problem constants ----------------
#define DEPTH 2
#define DIM   1024
#define HEADS 16
#define DH    64
#define BATCH 8
#define NQ    256
#define JTOT  1088
#define MS    1024
#define MROWS (BATCH*NQ)    // 2048
#define CROWS (BATCH*JTOT)  // 8704
#define FFH   4096
#define SCALE 0.125f

// ---------------- scratch ----------------
__device__ float g_Q[MROWS * DIM];
__device__ float g_K[CROWS * DIM];
__device__ float g_V[CROWS * DIM];
__device__ float g_VT[(long)BATCH * DIM * JTOT];
__device__ float g_S[(long)BATCH * HEADS * NQ * JTOT];
__device__ float g_O[MROWS * DIM];
__device__ float g_H[(long)MROWS * 2 * FFH];
__device__ float g_Y[(long)MROWS * FFH];
__device__ float g_WqT[(long)DEPTH * DIM * DIM];
__device__ float g_WkT[(long)DEPTH * DIM * DIM];
__device__ float g_WvT[(long)DEPTH * DIM * DIM];
__device__ float g_WoT[(long)DEPTH * DIM * DIM];
__device__ float g_W1T[(long)DEPTH * 2 * FFH * DIM];
__device__ float g_W2T[(long)DEPTH * DIM * FFH];

// ---------------- ptx helpers ----------------
__device__ __forceinline__ float tf32r(float f) {
    uint32_t u;
    asm("cvt.rna.tf32.f32 %0, %1;" : "=r"(u) : "f"(f));
    return __uint_as_float(u);
}
__device__ __forceinline__ void ldsm4(uint32_t* r, uint32_t a) {
    asm volatile("ldmatrix.sync.aligned.m8n8.x4.shared.b16 {%0,%1,%2,%3}, [%4];"
                 : "=r"(r[0]), "=r"(r[1]), "=r"(r[2]), "=r"(r[3]) : "r"(a));
}
__device__ __forceinline__ void ldsm2(uint32_t* r, uint32_t a) {
    asm volatile("ldmatrix.sync.aligned.m8n8.x2.shared.b16 {%0,%1}, [%2];"
                 : "=r"(r[0]), "=r"(r[1]) : "r"(a));
}
__device__ __forceinline__ void mma_tf32(float* c, const uint32_t* a, const uint32_t* b) {
    asm volatile(
        "mma.sync.aligned.m16n8k8.row.col.f32.tf32.tf32.f32 "
        "{%0,%1,%2,%3}, {%4,%5,%6,%7}, {%8,%9}, {%0,%1,%2,%3};"
        : "+f"(c[0]), "+f"(c[1]), "+f"(c[2]), "+f"(c[3])
        : "r"(a[0]), "r"(a[1]), "r"(a[2]), "r"(a[3]), "r"(b[0]), "r"(b[1]));
}
__device__ __forceinline__ void cpa16(uint32_t d, const float* s) {
    asm volatile("cp.async.cg.shared.global [%0], [%1], 16;" :: "r"(d), "l"(s));
}

// ---------------- tf32 tensor-core GEMM, ldmatrix + cp.async 3-stage ---------
// C[z] = alpha * A[z] @ B[z]^T (+ bias) (+ Cadd)
// A: [M][K] row-major (lda). B: [N][K] row-major (ldb) — i.e. "n-major".
// BM=128, BK=32. BN in {128,64}. 256 threads.
template <int BN>
__global__ void __launch_bounds__(256)
gemm_tc(const float* __restrict__ A, const float* __restrict__ B,
        float* __restrict__ C, const float* __restrict__ Cadd,
        const float* __restrict__ bias,
        int K, int lda, int ldb, int ldc,
        long long sA1, long long sA2,
        long long sB1, long long sB2,
        long long sC1, long long sC2,
        int HB, float alpha)
{
    constexpr int BM = 128, STAGES = 3;
    constexpr int ASZ = BM * 32, BSZ = BN * 32, STF = ASZ + BSZ;  // floats/stage
    constexpr int WN = (BN == 128) ? 4 : 2;
    constexpr int WM = 8 / WN;
    constexpr int WTM = BM / WM, WTN = BN / WN;
    constexpr int MI = WTM / 16, NI = WTN / 8;

    extern __shared__ float smdyn[];
    const uint32_t sb = (uint32_t)__cvta_generic_to_shared(smdyn);

    const int z = blockIdx.z;
    const int zb = z / HB, zh = z - zb * HB;
    A += zb * sA1 + zh * sA2;
    B += zb * sB1 + zh * sB2;
    C += zb * sC1 + zh * sC2;
    if (Cadd) Cadd += zb * sC1 + zh * sC2;

    const int tid = threadIdx.x, warp = tid >> 5, lane = tid & 31;
    const int wm = warp / WN, wn = warp % WN;
    const int g = lane >> 2, t = lane & 3;
    const int bm0 = blockIdx.y * BM, bn0 = blockIdx.x * BN;

    const int arow = tid >> 3;        // 0..31
    const int cc   = tid & 7;         // 16B chunk within 128B row

    const float* Ag = A + (long long)(bm0 + arow) * lda + cc * 4;
    const float* Bg = B + (long long)(bn0 + arow) * ldb + cc * 4;

    const int KT = K >> 5;

    auto load_stage = [&](int s, int kt) {
        if (kt < KT) {
            const int k0 = kt << 5;
            uint32_t ab = sb + (uint32_t)(s * STF) * 4u;
            #pragma unroll
            for (int i = 0; i < 4; i++) {
                int r = arow + i * 32;
                cpa16(ab + r * 128 + ((cc ^ (r & 7)) << 4),
                      Ag + (long long)i * 32 * lda + k0);
            }
            uint32_t bb = sb + (uint32_t)(s * STF + ASZ) * 4u;
            #pragma unroll
            for (int i = 0; i < BN / 32; i++) {
                int r = arow + i * 32;
                cpa16(bb + r * 128 + ((cc ^ (r & 7)) << 4),
                      Bg + (long long)i * 32 * ldb + k0);
            }
        }
        asm volatile("cp.async.commit_group;");
    };

    float acc[MI][NI][4];
    #pragma unroll
    for (int mi = 0; mi < MI; mi++)
        #pragma unroll
        for (int ni = 0; ni < NI; ni++)
            #pragma unroll
            for (int q = 0; q < 4; q++) acc[mi][ni][q] = 0.f;

    // ldmatrix lane geometry
    const int a_r  = lane & 15;         // row within 16-row tile
    const int a_kc = lane >> 4;         // +0/+1 chunk (k/4)
    const int b_r  = lane & 7;
    const int b_kc = (lane >> 3) & 1;

    load_stage(0, 0);
    load_stage(1, 1);

    for (int kt = 0; kt < KT; kt++) {
        asm volatile("cp.async.wait_group 1;");
        __syncthreads();
        load_stage((kt + 2) % 3, kt + 2);

        const int s = kt % 3;
        const uint32_t ab = sb + (uint32_t)(s * STF) * 4u;
        const uint32_t bb = ab + (uint32_t)ASZ * 4u;

        #pragma unroll
        for (int kk = 0; kk < 4; kk++) {          // 4 x k8 per 32-k tile
            uint32_t af[MI][4], bf[NI][2];
            #pragma unroll
            for (int mi = 0; mi < MI; mi++) {
                int r = wm * WTM + mi * 16 + a_r;
                int kc = kk * 2 + a_kc;
                ldsm4(af[mi], ab + r * 128 + ((kc ^ (r & 7)) << 4));
            }
            #pragma unroll
            for (int ni = 0; ni < NI; ni++) {
                int r = wn * WTN + ni * 8 + b_r;
                int kc = kk * 2 + b_kc;
                ldsm2(bf[ni], bb + r * 128 + ((kc ^ (r & 7)) << 4));
            }
            #pragma unroll
            for (int mi = 0; mi < MI; mi++)
                #pragma unroll
                for (int ni = 0; ni < NI; ni++)
                    mma_tf32(acc[mi][ni], af[mi], bf[ni]);
        }
        __syncthreads();
    }

    // epilogue
    #pragma unroll
    for (int mi = 0; mi < MI; mi++) {
        int row0 = bm0 + wm * WTM + mi * 16 + g;
        #pragma unroll
        for (int ni = 0; ni < NI; ni++) {
            int col = bn0 + wn * WTN + ni * 8 + 2 * t;
            float v0 = alpha * acc[mi][ni][0];
            float v1 = alpha * acc[mi][ni][1];
            float v2 = alpha * acc[mi][ni][2];
            float v3 = alpha * acc[mi][ni][3];
            if (bias) { float b0 = bias[col], b1 = bias[col + 1]; v0 += b0; v1 += b1; v2 += b0; v3 += b1; }
            if (Cadd) {
                const float2 c0 = *(const float2*)(Cadd + (long long)row0 * ldc + col);
                const float2 c1 = *(const float2*)(Cadd + (long long)(row0 + 8) * ldc + col);
                v0 += c0.x; v1 += c0.y; v2 += c1.x; v3 += c1.y;
            }
            *(float2*)(C + (long long)row0 * ldc + col) = make_float2(v0, v1);
            *(float2*)(C + (long long)(row0 + 8) * ldc + col) = make_float2(v2, v3);
        }
    }
}

// ---------------- tiled transpose with tf32 rounding ----------------
// in: [R][C] row-major (+ z*sIn) -> out: [C][R] row-major (+ z*sOut)
__global__ void transpose_cvt(const float* __restrict__ in, float* __restrict__ out,
                              int R, int C, long long sIn, long long sOut)
{
    __shared__ float tbuf[32][33];
    in  += (long long)blockIdx.z * sIn;
    out += (long long)blockIdx.z * sOut;
    int c0 = blockIdx.x * 32, r0 = blockIdx.y * 32;
    int x = threadIdx.x, y = threadIdx.y;
    #pragma unroll
    for (int i = 0; i < 32; i += 8)
        tbuf[y + i][x] = in[(long long)(r0 + y + i) * C + c0 + x];
    __syncthreads();
    #pragma unroll
    for (int i = 0; i < 32; i += 8)
        out[(long long)(c0 + y + i) * R + r0 + x] = tf32r(tbuf[x][y + i]);
}

// ---------------- rotary on Q ----------------
__global__ void rope_q_kernel(float* __restrict__ Q, const float* __restrict__ src_freq)
{
    long idx = (long)blockIdx.x * blockDim.x + threadIdx.x;
    if (idx >= (long)MROWS * (DIM / 2)) return;
    int row = (int)(idx >> 9);
    int pd  = (int)(idx & 511);
    int col = pd * 2;
    int n = row & (NQ - 1);
    int d = col & (DH - 1);
    float f0 = src_freq[n * DH + d];
    float f1 = src_freq[n * DH + d + 1];
    float* p = Q + (long long)row * DIM + col;
    float q0 = p[0], q1 = p[1];
    p[0] = q0 * cosf(f0) - q1 * sinf(f0);
    p[1] = q1 * cosf(f1) + q0 * sinf(f1);
}

// ---------------- RPE bias + rotary on memory K (tf32-rounded output) --------
__global__ void rope_bias_k_kernel(float* __restrict__ K,
                                   const float* __restrict__ tgt_freq,
                                   const float* __restrict__ rpe_l,
                                   const int* __restrict__ rel_idx)
{
    long idx = (long)blockIdx.x * blockDim.x + threadIdx.x;
    if (idx >= (long)BATCH * MS * (DIM / 2)) return;
    int b  = (int)(idx / ((long)MS * (DIM / 2)));
    int r  = (int)(idx % ((long)MS * (DIM / 2)));
    int j  = r >> 9;
    int pd = r & 511;
    int col = pd * 2;
    int h = col >> 6;
    int d = col & (DH - 1);
    int mem = j >> 8;
    float bias = rpe_l[rel_idx[mem] * HEADS + h];
    float f0 = tgt_freq[j * DH + d];
    float f1 = tgt_freq[j * DH + d + 1];
    float* p = K + ((long long)b * JTOT + j) * DIM + col;
    float k0 = p[0] + bias, k1 = p[1] + bias;
    p[0] = tf32r(k0 * cosf(f0) - k1 * sinf(f0));
    p[1] = tf32r(k1 * cosf(f1) + k0 * sinf(f1));
}

// ---------------- row softmax ----------------
__inline__ __device__ float warpMax(float v) {
    #pragma unroll
    for (int o = 16; o > 0; o >>= 1) v = fmaxf(v, __shfl_xor_sync(0xffffffffu, v, o));
    return v;
}
__inline__ __device__ float warpSum(float v) {
    #pragma unroll
    for (int o = 16; o > 0; o >>= 1) v += __shfl_xor_sync(0xffffffffu, v, o);
    return v;
}

__global__ void softmax_rows(float* __restrict__ S, int n)
{
    long row = blockIdx.x;
    float* p = S + row * n;
    int tid = threadIdx.x;
    int wid = tid >> 5, lane = tid & 31;
    __shared__ float red[4];

    float v[9];
    int cnt = 0;
    float m = -INFINITY;
    for (int j = tid; j < n; j += 128) {
        v[cnt] = p[j];
        m = fmaxf(m, v[cnt]);
        cnt++;
    }
    m = warpMax(m);
    if (lane == 0) red[wid] = m;
    __syncthreads();
    m = fmaxf(fmaxf(red[0], red[1]), fmaxf(red[2], red[3]));

    float s = 0.f;
    for (int i = 0; i < cnt; i++) { v[i] = expf(v[i] - m); s += v[i]; }
    s = warpSum(s);
    __syncthreads();
    if (lane == 0) red[wid] = s;
    __syncthreads();
    s = red[0] + red[1] + red[2] + red[3];
    float inv = 1.0f / s;

    int i = 0;
    for (int j = tid; j < n; j += 128) p[j] = v[i++] * inv;
}

// ---------------- GEGLU ----------------
__global__ void geglu_kernel(const float* __restrict__ H, float* __restrict__ Y)
{
    long idx = (long)blockIdx.x * blockDim.x + threadIdx.x;
    if (idx >= (long)MROWS * FFH) return;
    int row = (int)(idx >> 12);
    int c   = (int)(idx & (FFH - 1));
    const float* hr = H + (long long)row * (2 * FFH);
    float a = hr[c];
    float gg = hr[FFH + c];
    float ge = 0.5f * gg * (1.0f + erff(gg * 0.70710678118654752f));
    Y[idx] = a * ge;
}

// ---------------- launcher ----------------
extern "C" void kernel_launch(void* const* d_in, const int* in_sizes, int n_in,
                              void* d_out, int out_size)
{
    const float* x    = (const float*)d_in[0];
    const float* cond = (const float*)d_in[1];
    const float* Wq   = (const float*)d_in[2];
    const float* Wk   = (const float*)d_in[3];
    const float* Wv   = (const float*)d_in[4];
    const float* Wo   = (const float*)d_in[5];
    const float* bo   = (const float*)d_in[6];
    const float* rpe  = (const float*)d_in[7];
    const float* W1   = (const float*)d_in[8];
    const float* b1   = (const float*)d_in[9];
    const float* W2   = (const float*)d_in[10];
    const float* b2   = (const float*)d_in[11];
    const float* srcf = (const float*)d_in[12];
    const float* tgtf = (const float*)d_in[13];
    const int*   reli = (const int*)d_in[14];
    float* xo = (float*)d_out;

    float *Q, *K, *V, *VT, *S, *O, *H, *Y;
    float *WqT, *WkT, *WvT, *WoT, *W1T, *W2T;
    cudaGetSymbolAddress((void**)&Q, g_Q);
    cudaGetSymbolAddress((void**)&K, g_K);
    cudaGetSymbolAddress((void**)&V, g_V);
    cudaGetSymbolAddress((void**)&VT, g_VT);
    cudaGetSymbolAddress((void**)&S, g_S);
    cudaGetSymbolAddress((void**)&O, g_O);
    cudaGetSymbolAddress((void**)&H, g_H);
    cudaGetSymbolAddress((void**)&Y, g_Y);
    cudaGetSymbolAddress((void**)&WqT, g_WqT);
    cudaGetSymbolAddress((void**)&WkT, g_WkT);
    cudaGetSymbolAddress((void**)&WvT, g_WvT);
    cudaGetSymbolAddress((void**)&WoT, g_WoT);
    cudaGetSymbolAddress((void**)&W1T, g_W1T);
    cudaGetSymbolAddress((void**)&W2T, g_W2T);

    const int SM128 = (128 * 32 + 128 * 32) * 3 * 4;   // 96 KB
    const int SM64  = (128 * 32 + 64 * 32) * 3 * 4;    // 72 KB
    cudaFuncSetAttribute(gemm_tc<128>, cudaFuncAttributeMaxDynamicSharedMemorySize, SM128);
    cudaFuncSetAttribute(gemm_tc<64>,  cudaFuncAttributeMaxDynamicSharedMemorySize, SM64);

    cudaMemcpyAsync(xo, x, (size_t)MROWS * DIM * sizeof(float),
                    cudaMemcpyDeviceToDevice, 0);

    // ---- pre-transpose all weights (batched over DEPTH) ----
    dim3 tb(32, 8);
    transpose_cvt<<<dim3(32, 32, DEPTH), tb>>>(Wq, WqT, DIM, DIM, (long long)DIM*DIM, (long long)DIM*DIM);
    transpose_cvt<<<dim3(32, 32, DEPTH), tb>>>(Wk, WkT, DIM, DIM, (long long)DIM*DIM, (long long)DIM*DIM);
    transpose_cvt<<<dim3(32, 32, DEPTH), tb>>>(Wv, WvT, DIM, DIM, (long long)DIM*DIM, (long long)DIM*DIM);
    transpose_cvt<<<dim3(32, 32, DEPTH), tb>>>(Wo, WoT, DIM, DIM, (long long)DIM*DIM, (long long)DIM*DIM);
    transpose_cvt<<<dim3(2 * FFH / 32, 32, DEPTH), tb>>>(W1, W1T, DIM, 2 * FFH, (long long)DIM*2*FFH, (long long)DIM*2*FFH);
    transpose_cvt<<<dim3(32, FFH / 32, DEPTH), tb>>>(W2, W2T, FFH, DIM, (long long)FFH*DIM, (long long)FFH*DIM);

    const long long SBH = (long long)NQ * JTOT;
    const long long SB  = SBH * HEADS;

    for (int l = 0; l < DEPTH; l++) {
        const float* wqt = WqT + (long long)l * DIM * DIM;
        const float* wkt = WkT + (long long)l * DIM * DIM;
        const float* wvt = WvT + (long long)l * DIM * DIM;
        const float* wot = WoT + (long long)l * DIM * DIM;
        const float* bol = bo + l * DIM;
        const float* rpel = rpe + (long long)l * 405 * HEADS;
        const float* w1t = W1T + (long long)l * DIM * 2 * FFH;
        const float* b1l = b1 + (long long)l * (2 * FFH);
        const float* w2t = W2T + (long long)l * DIM * FFH;
        const float* b2l = b2 + l * DIM;

        // Q = x @ Wq
        gemm_tc<128><<<dim3(DIM / 128, MROWS / 128, 1), 256, SM128>>>(
            xo, wqt, Q, nullptr, nullptr,
            DIM, DIM, DIM, DIM, 0, 0, 0, 0, 0, 0, 1, 1.0f);
        // K = cond @ Wk
        gemm_tc<128><<<dim3(DIM / 128, CROWS / 128, 1), 256, SM128>>>(
            cond, wkt, K, nullptr, nullptr,
            DIM, DIM, DIM, DIM, 0, 0, 0, 0, 0, 0, 1, 1.0f);
        // V = cond @ Wv
        gemm_tc<128><<<dim3(DIM / 128, CROWS / 128, 1), 256, SM128>>>(
            cond, wvt, V, nullptr, nullptr,
            DIM, DIM, DIM, DIM, 0, 0, 0, 0, 0, 0, 1, 1.0f);

        // rotary on Q; bias+rotary on memory K
        rope_q_kernel<<<(MROWS * (DIM / 2) + 255) / 256, 256>>>(Q, srcf);
        rope_bias_k_kernel<<<(BATCH * MS * (DIM / 2) + 255) / 256, 256>>>(K, tgtf, rpel, reli);

        // V^T per batch: [JTOT][DIM] -> [DIM][JTOT]
        transpose_cvt<<<dim3(DIM / 32, JTOT / 32, BATCH), tb>>>(
            V, VT, JTOT, DIM, (long long)JTOT * DIM, (long long)DIM * JTOT);

        // S = SCALE * Q @ K^T (K already n-major over j)
        gemm_tc<64><<<dim3(JTOT / 64, NQ / 128, BATCH * HEADS), 256, SM64>>>(
            Q, K, S, nullptr, nullptr,
            DH, DIM, DIM, JTOT,
            (long long)NQ * DIM, DH,
            (long long)JTOT * DIM, DH,
            SB, SBH, HEADS, SCALE);

        softmax_rows<<<BATCH * HEADS * NQ, 128>>>(S, JTOT);

        // O = P @ V  (B = V^T, n-major over d)
        gemm_tc<64><<<dim3(1, NQ / 128, BATCH * HEADS), 256, SM64>>>(
            S, VT, O, nullptr, nullptr,
            JTOT, JTOT, JTOT, DIM,
            SB, SBH,
            (long long)DIM * JTOT, (long long)DH * JTOT,
            (long long)NQ * DIM, DH, HEADS, 1.0f);

        // x = x + O @ Wo + bo
        gemm_tc<128><<<dim3(DIM / 128, MROWS / 128, 1), 256, SM128>>>(
            O, wot, xo, xo, bol,
            DIM, DIM, DIM, DIM, 0, 0, 0, 0, 0, 0, 1, 1.0f);

        // H = x @ W1 + b1
        gemm_tc<128><<<dim3(2 * FFH / 128, MROWS / 128, 1), 256, SM128>>>(
            xo, w1t, H, nullptr, b1l,
            DIM, DIM, DIM, 2 * FFH, 0, 0, 0, 0, 0, 0, 1, 1.0f);

        // GEGLU
        geglu_kernel<<<((long)MROWS * FFH + 255) / 256, 256>>>(H, Y);

        // x = x + Y @ W2 + b2
        gemm_tc<128><<<dim3(DIM / 128, MROWS / 128, 1), 256, SM128>>>(
            Y, w2t, xo, xo, b2l,
            FFH, FFH, FFH, DIM, 0, 0, 0, 0, 0, 0, 1, 1.0f);
    }
}

// round 4
// speedup vs baseline: 4.5008x; 1.1824x over previous
#include <cuda_runtime.h>
#include <math.h>
#include <stdint.h>

// ---------------- problem constants ----------------
#define DEPTH 2
#define DIM   1024
#define HEADS 16
#define DH    64
#define BATCH 8
#define NQ    256
#define JTOT  1088
#define MS    1024
#define MROWS (BATCH*NQ)    // 2048
#define CROWS (BATCH*JTOT)  // 8704
#define FFH   4096
#define SCALE 0.125f
#define NJT   17            // JTOT / 64

// ---------------- scratch ----------------
__device__ float g_Q[MROWS * DIM];
__device__ float g_K[CROWS * DIM];
__device__ float g_V[CROWS * DIM];
__device__ float g_VT[(long)BATCH * DIM * JTOT];
__device__ float g_O[MROWS * DIM];
__device__ float g_Y[(long)MROWS * FFH];
__device__ float g_WqT[(long)DEPTH * DIM * DIM];
__device__ float g_WkT[(long)DEPTH * DIM * DIM];
__device__ float g_WvT[(long)DEPTH * DIM * DIM];
__device__ float g_WoT[(long)DEPTH * DIM * DIM];
__device__ float g_W1T[(long)DEPTH * 2 * FFH * DIM];
__device__ float g_W2T[(long)DEPTH * DIM * FFH];

// ---------------- ptx helpers ----------------
__device__ __forceinline__ float tf32r(float f) {
    uint32_t u;
    asm("cvt.rna.tf32.f32 %0, %1;" : "=r"(u) : "f"(f));
    return __uint_as_float(u);
}
__device__ __forceinline__ void ldsm4(uint32_t* r, uint32_t a) {
    asm volatile("ldmatrix.sync.aligned.m8n8.x4.shared.b16 {%0,%1,%2,%3}, [%4];"
                 : "=r"(r[0]), "=r"(r[1]), "=r"(r[2]), "=r"(r[3]) : "r"(a));
}
__device__ __forceinline__ void ldsm2(uint32_t* r, uint32_t a) {
    asm volatile("ldmatrix.sync.aligned.m8n8.x2.shared.b16 {%0,%1}, [%2];"
                 : "=r"(r[0]), "=r"(r[1]) : "r"(a));
}
__device__ __forceinline__ void mma_tf32(float* c, const uint32_t* a, const uint32_t* b) {
    asm volatile(
        "mma.sync.aligned.m16n8k8.row.col.f32.tf32.tf32.f32 "
        "{%0,%1,%2,%3}, {%4,%5,%6,%7}, {%8,%9}, {%0,%1,%2,%3};"
        : "+f"(c[0]), "+f"(c[1]), "+f"(c[2]), "+f"(c[3])
        : "r"(a[0]), "r"(a[1]), "r"(a[2]), "r"(a[3]), "r"(b[0]), "r"(b[1]));
}
__device__ __forceinline__ void mma_tf32b(float* c, const uint32_t* a, uint32_t b0, uint32_t b1) {
    asm volatile(
        "mma.sync.aligned.m16n8k8.row.col.f32.tf32.tf32.f32 "
        "{%0,%1,%2,%3}, {%4,%5,%6,%7}, {%8,%9}, {%0,%1,%2,%3};"
        : "+f"(c[0]), "+f"(c[1]), "+f"(c[2]), "+f"(c[3])
        : "r"(a[0]), "r"(a[1]), "r"(a[2]), "r"(a[3]), "r"(b0), "r"(b1));
}
__device__ __forceinline__ void cpa16(uint32_t d, const float* s) {
    asm volatile("cp.async.cg.shared.global [%0], [%1], 16;" :: "r"(d), "l"(s));
}

// ---------------- tf32 GEMM (unchanged from R3) ----------------
template <int BN>
__global__ void __launch_bounds__(256)
gemm_tc(const float* __restrict__ A, const float* __restrict__ B,
        float* __restrict__ C, const float* __restrict__ Cadd,
        const float* __restrict__ bias,
        int K, int lda, int ldb, int ldc,
        long long sA1, long long sA2,
        long long sB1, long long sB2,
        long long sC1, long long sC2,
        int HB, float alpha)
{
    constexpr int BM = 128;
    constexpr int ASZ = BM * 32, BSZ = BN * 32, STF = ASZ + BSZ;
    constexpr int WN = (BN == 128) ? 4 : 2;
    constexpr int WM = 8 / WN;
    constexpr int WTM = BM / WM, WTN = BN / WN;
    constexpr int MI = WTM / 16, NI = WTN / 8;

    extern __shared__ float smdyn[];
    const uint32_t sb = (uint32_t)__cvta_generic_to_shared(smdyn);

    const int z = blockIdx.z;
    const int zb = z / HB, zh = z - zb * HB;
    A += zb * sA1 + zh * sA2;
    B += zb * sB1 + zh * sB2;
    C += zb * sC1 + zh * sC2;
    if (Cadd) Cadd += zb * sC1 + zh * sC2;

    const int tid = threadIdx.x, warp = tid >> 5, lane = tid & 31;
    const int wm = warp / WN, wn = warp % WN;
    const int g = lane >> 2, t = lane & 3;
    const int bm0 = blockIdx.y * BM, bn0 = blockIdx.x * BN;

    const int arow = tid >> 3;
    const int cc   = tid & 7;

    const float* Ag = A + (long long)(bm0 + arow) * lda + cc * 4;
    const float* Bg = B + (long long)(bn0 + arow) * ldb + cc * 4;

    const int KT = K >> 5;

    auto load_stage = [&](int s, int kt) {
        if (kt < KT) {
            const int k0 = kt << 5;
            uint32_t ab = sb + (uint32_t)(s * STF) * 4u;
            #pragma unroll
            for (int i = 0; i < 4; i++) {
                int r = arow + i * 32;
                cpa16(ab + r * 128 + ((cc ^ (r & 7)) << 4),
                      Ag + (long long)i * 32 * lda + k0);
            }
            uint32_t bb = sb + (uint32_t)(s * STF + ASZ) * 4u;
            #pragma unroll
            for (int i = 0; i < BN / 32; i++) {
                int r = arow + i * 32;
                cpa16(bb + r * 128 + ((cc ^ (r & 7)) << 4),
                      Bg + (long long)i * 32 * ldb + k0);
            }
        }
        asm volatile("cp.async.commit_group;");
    };

    float acc[MI][NI][4];
    #pragma unroll
    for (int mi = 0; mi < MI; mi++)
        #pragma unroll
        for (int ni = 0; ni < NI; ni++)
            #pragma unroll
            for (int q = 0; q < 4; q++) acc[mi][ni][q] = 0.f;

    const int a_r  = lane & 15;
    const int a_kc = lane >> 4;
    const int b_r  = lane & 7;
    const int b_kc = (lane >> 3) & 1;

    load_stage(0, 0);
    load_stage(1, 1);

    for (int kt = 0; kt < KT; kt++) {
        asm volatile("cp.async.wait_group 1;");
        __syncthreads();
        load_stage((kt + 2) % 3, kt + 2);

        const int s = kt % 3;
        const uint32_t ab = sb + (uint32_t)(s * STF) * 4u;
        const uint32_t bb = ab + (uint32_t)ASZ * 4u;

        #pragma unroll
        for (int kk = 0; kk < 4; kk++) {
            uint32_t af[MI][4], bf[NI][2];
            #pragma unroll
            for (int mi = 0; mi < MI; mi++) {
                int r = wm * WTM + mi * 16 + a_r;
                int kc = kk * 2 + a_kc;
                ldsm4(af[mi], ab + r * 128 + ((kc ^ (r & 7)) << 4));
            }
            #pragma unroll
            for (int ni = 0; ni < NI; ni++) {
                int r = wn * WTN + ni * 8 + b_r;
                int kc = kk * 2 + b_kc;
                ldsm2(bf[ni], bb + r * 128 + ((kc ^ (r & 7)) << 4));
            }
            #pragma unroll
            for (int mi = 0; mi < MI; mi++)
                #pragma unroll
                for (int ni = 0; ni < NI; ni++)
                    mma_tf32(acc[mi][ni], af[mi], bf[ni]);
        }
        __syncthreads();
    }

    #pragma unroll
    for (int mi = 0; mi < MI; mi++) {
        int row0 = bm0 + wm * WTM + mi * 16 + g;
        #pragma unroll
        for (int ni = 0; ni < NI; ni++) {
            int col = bn0 + wn * WTN + ni * 8 + 2 * t;
            float v0 = alpha * acc[mi][ni][0];
            float v1 = alpha * acc[mi][ni][1];
            float v2 = alpha * acc[mi][ni][2];
            float v3 = alpha * acc[mi][ni][3];
            if (bias) { float b0 = bias[col], b1 = bias[col + 1]; v0 += b0; v1 += b1; v2 += b0; v3 += b1; }
            if (Cadd) {
                const float2 c0 = *(const float2*)(Cadd + (long long)row0 * ldc + col);
                const float2 c1 = *(const float2*)(Cadd + (long long)(row0 + 8) * ldc + col);
                v0 += c0.x; v1 += c0.y; v2 += c1.x; v3 += c1.y;
            }
            *(float2*)(C + (long long)row0 * ldc + col) = make_float2(v0, v1);
            *(float2*)(C + (long long)(row0 + 8) * ldc + col) = make_float2(v2, v3);
        }
    }
}

// ---------------- FFN1 + GEGLU fused ----------------
// Y[m, c] = (x@W1a + b1a)[m,c] * gelu((x@W1g + b1g)[m,c])
// A = x [2048][1024]; B = W1T rows: a at [bn0..], g at [FFH+bn0..]
__global__ void __launch_bounds__(256)
gemm_ffn1(const float* __restrict__ A, const float* __restrict__ B,
          float* __restrict__ Y, const float* __restrict__ b1l)
{
    constexpr int BM = 128, BN = 64;
    constexpr int ASZ = BM * 32, BSZ = BN * 32, STF = ASZ + 2 * BSZ;  // 8192 floats
    constexpr int WTM = 32, WTN = 32, MI = 2, NI = 4;
    const int KT = 32;  // K=1024

    extern __shared__ float smdyn[];
    const uint32_t sb = (uint32_t)__cvta_generic_to_shared(smdyn);

    const int tid = threadIdx.x, warp = tid >> 5, lane = tid & 31;
    const int wm = warp >> 1, wn = warp & 1;
    const int g = lane >> 2, t = lane & 3;
    const int bm0 = blockIdx.y * BM, bn0 = blockIdx.x * BN;

    const int arow = tid >> 3;
    const int cc   = tid & 7;

    const float* Ag  = A + (long long)(bm0 + arow) * DIM + cc * 4;
    const float* Bga = B + (long long)(bn0 + arow) * DIM + cc * 4;
    const float* Bgg = B + (long long)(FFH + bn0 + arow) * DIM + cc * 4;

    auto load_stage = [&](int s, int kt) {
        if (kt < KT) {
            const int k0 = kt << 5;
            uint32_t ab = sb + (uint32_t)(s * STF) * 4u;
            #pragma unroll
            for (int i = 0; i < 4; i++) {
                int r = arow + i * 32;
                cpa16(ab + r * 128 + ((cc ^ (r & 7)) << 4),
                      Ag + (long long)i * 32 * DIM + k0);
            }
            uint32_t bba = sb + (uint32_t)(s * STF + ASZ) * 4u;
            uint32_t bbg = bba + (uint32_t)BSZ * 4u;
            #pragma unroll
            for (int i = 0; i < 2; i++) {
                int r = arow + i * 32;
                cpa16(bba + r * 128 + ((cc ^ (r & 7)) << 4),
                      Bga + (long long)i * 32 * DIM + k0);
                cpa16(bbg + r * 128 + ((cc ^ (r & 7)) << 4),
                      Bgg + (long long)i * 32 * DIM + k0);
            }
        }
        asm volatile("cp.async.commit_group;");
    };

    float acca[MI][NI][4], accg[MI][NI][4];
    #pragma unroll
    for (int mi = 0; mi < MI; mi++)
        #pragma unroll
        for (int ni = 0; ni < NI; ni++)
            #pragma unroll
            for (int q = 0; q < 4; q++) { acca[mi][ni][q] = 0.f; accg[mi][ni][q] = 0.f; }

    const int a_r  = lane & 15;
    const int a_kc = lane >> 4;
    const int b_r  = lane & 7;
    const int b_kc = (lane >> 3) & 1;

    load_stage(0, 0);
    load_stage(1, 1);

    for (int kt = 0; kt < KT; kt++) {
        asm volatile("cp.async.wait_group 1;");
        __syncthreads();
        load_stage((kt + 2) % 3, kt + 2);

        const int s = kt % 3;
        const uint32_t ab  = sb + (uint32_t)(s * STF) * 4u;
        const uint32_t bba = ab + (uint32_t)ASZ * 4u;
        const uint32_t bbg = bba + (uint32_t)BSZ * 4u;

        #pragma unroll
        for (int kk = 0; kk < 4; kk++) {
            uint32_t af[MI][4], bfa[NI][2], bfg[NI][2];
            #pragma unroll
            for (int mi = 0; mi < MI; mi++) {
                int r = wm * WTM + mi * 16 + a_r;
                int kc = kk * 2 + a_kc;
                ldsm4(af[mi], ab + r * 128 + ((kc ^ (r & 7)) << 4));
            }
            #pragma unroll
            for (int ni = 0; ni < NI; ni++) {
                int r = wn * WTN + ni * 8 + b_r;
                int kc = kk * 2 + b_kc;
                ldsm2(bfa[ni], bba + r * 128 + ((kc ^ (r & 7)) << 4));
                ldsm2(bfg[ni], bbg + r * 128 + ((kc ^ (r & 7)) << 4));
            }
            #pragma unroll
            for (int mi = 0; mi < MI; mi++)
                #pragma unroll
                for (int ni = 0; ni < NI; ni++) {
                    mma_tf32(acca[mi][ni], af[mi], bfa[ni]);
                    mma_tf32(accg[mi][ni], af[mi], bfg[ni]);
                }
        }
        __syncthreads();
    }

    #pragma unroll
    for (int mi = 0; mi < MI; mi++) {
        int row0 = bm0 + wm * WTM + mi * 16 + g;
        #pragma unroll
        for (int ni = 0; ni < NI; ni++) {
            int col = bn0 + wn * WTN + ni * 8 + 2 * t;
            float ba0 = b1l[col], ba1 = b1l[col + 1];
            float bg0 = b1l[FFH + col], bg1 = b1l[FFH + col + 1];
            #pragma unroll
            for (int half = 0; half < 2; half++) {
                float a0 = acca[mi][ni][half * 2 + 0] + ba0;
                float a1 = acca[mi][ni][half * 2 + 1] + ba1;
                float g0 = accg[mi][ni][half * 2 + 0] + bg0;
                float g1 = accg[mi][ni][half * 2 + 1] + bg1;
                float y0 = a0 * (0.5f * g0 * (1.0f + erff(g0 * 0.70710678118654752f)));
                float y1 = a1 * (0.5f * g1 * (1.0f + erff(g1 * 0.70710678118654752f)));
                *(float2*)(Y + (long long)(row0 + half * 8) * FFH + col) = make_float2(y0, y1);
            }
        }
    }
}

// ---------------- flash attention ----------------
// Q pre-scaled by SCALE (in rope_q). K rope/bias applied. VT = V^T per batch.
// grid: (NQ/128, BATCH*HEADS). 256 threads; warp w owns Q rows w*16..w*16+15.
__global__ void __launch_bounds__(256)
flash_attn(const float* __restrict__ Q, const float* __restrict__ K,
           const float* __restrict__ VT, float* __restrict__ O)
{
    extern __shared__ float sm[];
    const uint32_t sb = (uint32_t)__cvta_generic_to_shared(sm);
    const uint32_t qb = sb;                    // 8192 floats: [half][128][32]
    const uint32_t kb = sb + 8192u * 4u;       // 2 stages x 4096: [s][half][64][32]
    const uint32_t vb = sb + 16384u * 4u;      // same
    const uint32_t pb = sb + 24576u * 4u;      // 8192: [half][128][32]

    const int tid = threadIdx.x, warp = tid >> 5, lane = tid & 31;
    const int g = lane >> 2, t = lane & 3;
    const int m0 = blockIdx.x * 128;
    const int z = blockIdx.y;
    const int b = z >> 4, h = z & 15;

    const float* Qg = Q + ((long long)(b * NQ + m0)) * DIM + h * DH;
    const float* Kg = K + (long long)b * JTOT * DIM + h * DH;
    const float* Vg = VT + (long long)b * DIM * JTOT + (long long)h * DH * JTOT;
    float* Og = O + ((long long)(b * NQ + m0)) * DIM + h * DH;

    // ---- load Q (8 cpa16 per thread) ----
    #pragma unroll
    for (int i = 0; i < 8; i++) {
        int idx = tid + i * 256;
        int cc = idx & 7, r = (idx >> 3) & 127, hf = idx >> 10;
        cpa16(qb + (uint32_t)(hf * 128 + r) * 128u + ((cc ^ (r & 7)) << 4),
              Qg + (long long)r * DIM + hf * 32 + cc * 4);
    }

    auto load_kv = [&](int s, int jt) {
        if (jt < NJT) {
            #pragma unroll
            for (int i = 0; i < 4; i++) {
                int idx = tid + i * 256;
                int cc = idx & 7, r = (idx >> 3) & 63, hf = idx >> 9;
                uint32_t off = (uint32_t)(s * 4096 + (hf * 64 + r) * 32) * 4u + ((cc ^ (r & 7)) << 4);
                cpa16(kb + off, Kg + (long long)(jt * 64 + r) * DIM + hf * 32 + cc * 4);
                cpa16(vb + off, Vg + (long long)r * JTOT + jt * 64 + hf * 32 + cc * 4);
            }
        }
        asm volatile("cp.async.commit_group;");
    };

    load_kv(0, 0);          // group0 (includes Q)
    asm volatile("cp.async.commit_group;" ::: "memory");  // (empty group to keep count simple)
    load_kv(1, 1);          // next

    // NOTE: groups committed so far = 3 (g0: Q+kv0, g1: empty, g2: kv1)

    float acco[8][4];
    #pragma unroll
    for (int ni = 0; ni < 8; ni++)
        #pragma unroll
        for (int q = 0; q < 4; q++) acco[ni][q] = 0.f;
    float mr0 = -INFINITY, mr1 = -INFINITY, l0 = 0.f, l1 = 0.f;

    const int fr = lane & 15;       // ldmatrix row-in-16
    const int fc = lane >> 4;       // ldmatrix chunk sel

    for (int jt = 0; jt < NJT; jt++) {
        const int s = jt & 1;
        asm volatile("cp.async.wait_group 2;");
        __syncthreads();

        // ---- S = Q @ K^T ----
        float accs[8][4];
        #pragma unroll
        for (int ni = 0; ni < 8; ni++)
            #pragma unroll
            for (int q = 0; q < 4; q++) accs[ni][q] = 0.f;

        #pragma unroll
        for (int kk = 0; kk < 8; kk++) {
            const int hf = kk >> 2;
            const int kc = (kk & 3) * 2 + fc;
            uint32_t a[4];
            {
                int r = warp * 16 + fr;
                ldsm4(a, qb + (uint32_t)(hf * 128 + r) * 128u + ((kc ^ (r & 7)) << 4));
            }
            #pragma unroll
            for (int p = 0; p < 4; p++) {
                int r = p * 16 + fr;
                uint32_t bf[4];
                ldsm4(bf, kb + (uint32_t)(s * 4096 + (hf * 64 + r) * 32) * 4u + ((kc ^ (r & 7)) << 4));
                mma_tf32b(accs[2 * p],     a, bf[0], bf[2]);
                mma_tf32b(accs[2 * p + 1], a, bf[1], bf[3]);
            }
        }

        // ---- online softmax (rows g, g+8 within warp tile) ----
        float vm0 = -INFINITY, vm1 = -INFINITY;
        #pragma unroll
        for (int ni = 0; ni < 8; ni++) {
            vm0 = fmaxf(vm0, fmaxf(accs[ni][0], accs[ni][1]));
            vm1 = fmaxf(vm1, fmaxf(accs[ni][2], accs[ni][3]));
        }
        vm0 = fmaxf(vm0, __shfl_xor_sync(0xffffffffu, vm0, 1));
        vm0 = fmaxf(vm0, __shfl_xor_sync(0xffffffffu, vm0, 2));
        vm1 = fmaxf(vm1, __shfl_xor_sync(0xffffffffu, vm1, 1));
        vm1 = fmaxf(vm1, __shfl_xor_sync(0xffffffffu, vm1, 2));
        float mn0 = fmaxf(mr0, vm0), mn1 = fmaxf(mr1, vm1);
        float sc0 = __expf(mr0 - mn0), sc1 = __expf(mr1 - mn1);

        float ps0 = 0.f, ps1 = 0.f;
        float pv[8][4];
        #pragma unroll
        for (int ni = 0; ni < 8; ni++) {
            pv[ni][0] = tf32r(__expf(accs[ni][0] - mn0));
            pv[ni][1] = tf32r(__expf(accs[ni][1] - mn0));
            pv[ni][2] = tf32r(__expf(accs[ni][2] - mn1));
            pv[ni][3] = tf32r(__expf(accs[ni][3] - mn1));
            ps0 += pv[ni][0] + pv[ni][1];
            ps1 += pv[ni][2] + pv[ni][3];
        }
        ps0 += __shfl_xor_sync(0xffffffffu, ps0, 1);
        ps0 += __shfl_xor_sync(0xffffffffu, ps0, 2);
        ps1 += __shfl_xor_sync(0xffffffffu, ps1, 1);
        ps1 += __shfl_xor_sync(0xffffffffu, ps1, 2);
        l0 = l0 * sc0 + ps0;
        l1 = l1 * sc1 + ps1;
        mr0 = mn0; mr1 = mn1;
        #pragma unroll
        for (int ni = 0; ni < 8; ni++) {
            acco[ni][0] *= sc0; acco[ni][1] *= sc0;
            acco[ni][2] *= sc1; acco[ni][3] *= sc1;
        }

        // ---- store P to smem ----
        const int r0 = warp * 16 + g, r1 = r0 + 8;
        #pragma unroll
        for (int ni = 0; ni < 8; ni++) {
            int hf = ni >> 2;
            int cc = (ni & 3) * 2 + (t >> 1);
            uint32_t ofs = (uint32_t)((t & 1) * 8);
            uint32_t a0 = pb + (uint32_t)(hf * 128 + r0) * 128u + ((cc ^ (r0 & 7)) << 4) + ofs;
            uint32_t a1 = pb + (uint32_t)(hf * 128 + r1) * 128u + ((cc ^ (r1 & 7)) << 4) + ofs;
            asm volatile("st.shared.v2.f32 [%0], {%1,%2};" :: "r"(a0), "f"(pv[ni][0]), "f"(pv[ni][1]));
            asm volatile("st.shared.v2.f32 [%0], {%1,%2};" :: "r"(a1), "f"(pv[ni][2]), "f"(pv[ni][3]));
        }
        __syncthreads();

        // ---- O += P @ V ----
        #pragma unroll
        for (int kk = 0; kk < 8; kk++) {
            const int hf = kk >> 2;
            const int kc = (kk & 3) * 2 + fc;
            uint32_t a[4];
            {
                int r = warp * 16 + fr;
                ldsm4(a, pb + (uint32_t)(hf * 128 + r) * 128u + ((kc ^ (r & 7)) << 4));
            }
            #pragma unroll
            for (int p = 0; p < 4; p++) {
                int r = p * 16 + fr;
                uint32_t bf[4];
                ldsm4(bf, vb + (uint32_t)(s * 4096 + (hf * 64 + r) * 32) * 4u + ((kc ^ (r & 7)) << 4));
                mma_tf32b(acco[2 * p],     a, bf[0], bf[2]);
                mma_tf32b(acco[2 * p + 1], a, bf[1], bf[3]);
            }
        }
        __syncthreads();

        load_kv(s, jt + 2);
    }

    // ---- epilogue ----
    float inv0 = 1.f / l0, inv1 = 1.f / l1;
    const int r0 = warp * 16 + g, r1 = r0 + 8;
    #pragma unroll
    for (int ni = 0; ni < 8; ni++) {
        int col = ni * 8 + 2 * t;
        *(float2*)(Og + (long long)r0 * DIM + col) =
            make_float2(acco[ni][0] * inv0, acco[ni][1] * inv0);
        *(float2*)(Og + (long long)r1 * DIM + col) =
            make_float2(acco[ni][2] * inv1, acco[ni][3] * inv1);
    }
}

// ---------------- tiled transpose with tf32 rounding ----------------
__global__ void transpose_cvt(const float* __restrict__ in, float* __restrict__ out,
                              int R, int C, long long sIn, long long sOut)
{
    __shared__ float tbuf[32][33];
    in  += (long long)blockIdx.z * sIn;
    out += (long long)blockIdx.z * sOut;
    int c0 = blockIdx.x * 32, r0 = blockIdx.y * 32;
    int x = threadIdx.x, y = threadIdx.y;
    #pragma unroll
    for (int i = 0; i < 32; i += 8)
        tbuf[y + i][x] = in[(long long)(r0 + y + i) * C + c0 + x];
    __syncthreads();
    #pragma unroll
    for (int i = 0; i < 32; i += 8)
        out[(long long)(c0 + y + i) * R + r0 + x] = tf32r(tbuf[x][y + i]);
}

// ---------------- rotary on Q (with SCALE folded in) ----------------
__global__ void rope_q_kernel(float* __restrict__ Q, const float* __restrict__ src_freq)
{
    long idx = (long)blockIdx.x * blockDim.x + threadIdx.x;
    if (idx >= (long)MROWS * (DIM / 2)) return;
    int row = (int)(idx >> 9);
    int pd  = (int)(idx & 511);
    int col = pd * 2;
    int n = row & (NQ - 1);
    int d = col & (DH - 1);
    float f0 = src_freq[n * DH + d];
    float f1 = src_freq[n * DH + d + 1];
    float* p = Q + (long long)row * DIM + col;
    float q0 = p[0], q1 = p[1];
    p[0] = (q0 * cosf(f0) - q1 * sinf(f0)) * SCALE;
    p[1] = (q1 * cosf(f1) + q0 * sinf(f1)) * SCALE;
}

// ---------------- RPE bias + rotary on memory K ----------------
__global__ void rope_bias_k_kernel(float* __restrict__ K,
                                   const float* __restrict__ tgt_freq,
                                   const float* __restrict__ rpe_l,
                                   const int* __restrict__ rel_idx)
{
    long idx = (long)blockIdx.x * blockDim.x + threadIdx.x;
    if (idx >= (long)BATCH * MS * (DIM / 2)) return;
    int b  = (int)(idx / ((long)MS * (DIM / 2)));
    int r  = (int)(idx % ((long)MS * (DIM / 2)));
    int j  = r >> 9;
    int pd = r & 511;
    int col = pd * 2;
    int h = col >> 6;
    int d = col & (DH - 1);
    int mem = j >> 8;
    float bias = rpe_l[rel_idx[mem] * HEADS + h];
    float f0 = tgt_freq[j * DH + d];
    float f1 = tgt_freq[j * DH + d + 1];
    float* p = K + ((long long)b * JTOT + j) * DIM + col;
    float k0 = p[0] + bias, k1 = p[1] + bias;
    p[0] = tf32r(k0 * cosf(f0) - k1 * sinf(f0));
    p[1] = tf32r(k1 * cosf(f1) + k0 * sinf(f1));
}

// ---------------- launcher ----------------
extern "C" void kernel_launch(void* const* d_in, const int* in_sizes, int n_in,
                              void* d_out, int out_size)
{
    const float* x    = (const float*)d_in[0];
    const float* cond = (const float*)d_in[1];
    const float* Wq   = (const float*)d_in[2];
    const float* Wk   = (const float*)d_in[3];
    const float* Wv   = (const float*)d_in[4];
    const float* Wo   = (const float*)d_in[5];
    const float* bo   = (const float*)d_in[6];
    const float* rpe  = (const float*)d_in[7];
    const float* W1   = (const float*)d_in[8];
    const float* b1   = (const float*)d_in[9];
    const float* W2   = (const float*)d_in[10];
    const float* b2   = (const float*)d_in[11];
    const float* srcf = (const float*)d_in[12];
    const float* tgtf = (const float*)d_in[13];
    const int*   reli = (const int*)d_in[14];
    float* xo = (float*)d_out;

    float *Q, *K, *V, *VT, *O, *Y;
    float *WqT, *WkT, *WvT, *WoT, *W1T, *W2T;
    cudaGetSymbolAddress((void**)&Q, g_Q);
    cudaGetSymbolAddress((void**)&K, g_K);
    cudaGetSymbolAddress((void**)&V, g_V);
    cudaGetSymbolAddress((void**)&VT, g_VT);
    cudaGetSymbolAddress((void**)&O, g_O);
    cudaGetSymbolAddress((void**)&Y, g_Y);
    cudaGetSymbolAddress((void**)&WqT, g_WqT);
    cudaGetSymbolAddress((void**)&WkT, g_WkT);
    cudaGetSymbolAddress((void**)&WvT, g_WvT);
    cudaGetSymbolAddress((void**)&WoT, g_WoT);
    cudaGetSymbolAddress((void**)&W1T, g_W1T);
    cudaGetSymbolAddress((void**)&W2T, g_W2T);

    const int SM128  = (128 * 32 + 128 * 32) * 3 * 4;   // 96 KB
    const int SMF1   = (128 * 32 + 2 * 64 * 32) * 3 * 4; // 96 KB
    const int SMFL   = 32768 * 4;                        // 128 KB
    cudaFuncSetAttribute(gemm_tc<128>, cudaFuncAttributeMaxDynamicSharedMemorySize, SM128);
    cudaFuncSetAttribute(gemm_ffn1, cudaFuncAttributeMaxDynamicSharedMemorySize, SMF1);
    cudaFuncSetAttribute(flash_attn, cudaFuncAttributeMaxDynamicSharedMemorySize, SMFL);

    cudaMemcpyAsync(xo, x, (size_t)MROWS * DIM * sizeof(float),
                    cudaMemcpyDeviceToDevice, 0);

    // ---- pre-transpose all weights ----
    dim3 tb(32, 8);
    transpose_cvt<<<dim3(32, 32, DEPTH), tb>>>(Wq, WqT, DIM, DIM, (long long)DIM*DIM, (long long)DIM*DIM);
    transpose_cvt<<<dim3(32, 32, DEPTH), tb>>>(Wk, WkT, DIM, DIM, (long long)DIM*DIM, (long long)DIM*DIM);
    transpose_cvt<<<dim3(32, 32, DEPTH), tb>>>(Wv, WvT, DIM, DIM, (long long)DIM*DIM, (long long)DIM*DIM);
    transpose_cvt<<<dim3(32, 32, DEPTH), tb>>>(Wo, WoT, DIM, DIM, (long long)DIM*DIM, (long long)DIM*DIM);
    transpose_cvt<<<dim3(2 * FFH / 32, 32, DEPTH), tb>>>(W1, W1T, DIM, 2 * FFH, (long long)DIM*2*FFH, (long long)DIM*2*FFH);
    transpose_cvt<<<dim3(32, FFH / 32, DEPTH), tb>>>(W2, W2T, FFH, DIM, (long long)FFH*DIM, (long long)FFH*DIM);

    for (int l = 0; l < DEPTH; l++) {
        const float* wqt = WqT + (long long)l * DIM * DIM;
        const float* wkt = WkT + (long long)l * DIM * DIM;
        const float* wvt = WvT + (long long)l * DIM * DIM;
        const float* wot = WoT + (long long)l * DIM * DIM;
        const float* bol = bo + l * DIM;
        const float* rpel = rpe + (long long)l * 405 * HEADS;
        const float* w1t = W1T + (long long)l * DIM * 2 * FFH;
        const float* b1l = b1 + (long long)l * (2 * FFH);
        const float* w2t = W2T + (long long)l * DIM * FFH;
        const float* b2l = b2 + l * DIM;

        gemm_tc<128><<<dim3(DIM / 128, MROWS / 128, 1), 256, SM128>>>(
            xo, wqt, Q, nullptr, nullptr,
            DIM, DIM, DIM, DIM, 0, 0, 0, 0, 0, 0, 1, 1.0f);
        gemm_tc<128><<<dim3(DIM / 128, CROWS / 128, 1), 256, SM128>>>(
            cond, wkt, K, nullptr, nullptr,
            DIM, DIM, DIM, DIM, 0, 0, 0, 0, 0, 0, 1, 1.0f);
        gemm_tc<128><<<dim3(DIM / 128, CROWS / 128, 1), 256, SM128>>>(
            cond, wvt, V, nullptr, nullptr,
            DIM, DIM, DIM, DIM, 0, 0, 0, 0, 0, 0, 1, 1.0f);

        rope_q_kernel<<<(MROWS * (DIM / 2) + 255) / 256, 256>>>(Q, srcf);
        rope_bias_k_kernel<<<(BATCH * MS * (DIM / 2) + 255) / 256, 256>>>(K, tgtf, rpel, reli);

        transpose_cvt<<<dim3(DIM / 32, JTOT / 32, BATCH), tb>>>(
            V, VT, JTOT, DIM, (long long)JTOT * DIM, (long long)DIM * JTOT);

        // fused attention -> O
        flash_attn<<<dim3(NQ / 128, BATCH * HEADS), 256, SMFL>>>(Q, K, VT, O);

        // x = x + O @ Wo + bo
        gemm_tc<128><<<dim3(DIM / 128, MROWS / 128, 1), 256, SM128>>>(
            O, wot, xo, xo, bol,
            DIM, DIM, DIM, DIM, 0, 0, 0, 0, 0, 0, 1, 1.0f);

        // Y = GEGLU(x @ W1 + b1)
        gemm_ffn1<<<dim3(FFH / 64, MROWS / 128), 256, SMF1>>>(xo, w1t, Y, b1l);

        // x = x + Y @ W2 + b2
        gemm_tc<128><<<dim3(DIM / 128, MROWS / 128, 1), 256, SM128>>>(
            Y, w2t, xo, xo, b2l,
            FFH, FFH, FFH, DIM, 0, 0, 0, 0, 0, 0, 1, 1.0f);
    }
}